// round 13
// baseline (speedup 1.0000x reference)
#include <cuda_runtime.h>
#include <math.h>

#define C_CH   16
#define T_LEN  8192
#define F_LEN  16384
#define HF     8192
#define K_MODES 8
#define N_ITERS 19
#define ALPHA_F 2000.0f
#define NBLK   128
#define NTHR   1024

#define MODE_R 0   // all-float32: [u_out | Re(u_hat2) | Re(omega)] (2,097,312 f32) -- confirmed
#define MODE_C 1
#define MODE_M 2

#define FIXSCALE 67108864.0   // 2^26

// padded smem index: 1 extra float2 per 16 -> breaks power-of-2 stride conflicts
#define PHI(i) ((i) + ((i) >> 4))

// ---------------- device state ----------------
__device__ float2             g_work[C_CH][HF];      // forward-FFT workspace
__device__ float2             g_u2[128 * HF];        // u rows r=k*16+c_shifted, contiguous j
__device__ unsigned long long g_acc[N_ITERS][16];    // fixed-point global partial sums
__device__ unsigned           g_itcnt[N_ITERS];      // per-iteration arrival counters
__device__ float              g_omega[(N_ITERS + 1) * K_MODES];
__device__ unsigned           g_flags[NBLK];         // monotonic phase flags
__device__ unsigned           g_gen;                 // monotonic phase release
__device__ unsigned           g_epoch;               // advances by 3 per launch

// ---------------- complex helpers ----------------
__device__ __forceinline__ float2 cmulf(float2 a, float c, float s) {
    return make_float2(a.x * c - a.y * s, a.x * s + a.y * c);
}
__device__ __forceinline__ float2 cadd(float2 a, float2 b) { return make_float2(a.x + b.x, a.y + b.y); }
__device__ __forceinline__ float2 csub(float2 a, float2 b) { return make_float2(a.x - b.x, a.y - b.y); }

// ---------------- radix-8 butterfly core ----------
__device__ __forceinline__ void r8_core(float2* x, float cw, float sw, float sign) {
    const float c2 = cw * cw - sw * sw, s2 = 2.f * cw * sw;   // w^2
    const float c1 = c2 * c2 - s2 * s2, s1 = 2.f * c2 * s2;   // w^4
    float2 t1 = cmulf(x[1], c1, s1);
    float2 y0 = cadd(x[0], t1), y1 = csub(x[0], t1);
    float2 t3 = cmulf(x[3], c1, s1);
    float2 y2 = cadd(x[2], t3), y3 = csub(x[2], t3);
    float2 t5 = cmulf(x[5], c1, s1);
    float2 y4 = cadd(x[4], t5), y5 = csub(x[4], t5);
    float2 t7 = cmulf(x[7], c1, s1);
    float2 y6 = cadd(x[6], t7), y7 = csub(x[6], t7);
    const float fx = -sign * s2, fy = sign * c2;
    float2 u2 = cmulf(y2, c2, s2);
    float2 z0 = cadd(y0, u2), z2 = csub(y0, u2);
    float2 u3 = cmulf(y3, fx, fy);
    float2 z1 = cadd(y1, u3), z3 = csub(y1, u3);
    float2 u6 = cmulf(y6, c2, s2);
    float2 z4 = cadd(y4, u6), z6 = csub(y4, u6);
    float2 u7 = cmulf(y7, fx, fy);
    float2 z5 = cadd(y5, u7), z7 = csub(y5, u7);
    const float C45 = 0.70710678118654752440f;
    float2 v4 = cmulf(z4, cw, sw);
    float2 v5 = cmulf(z5, C45 * (cw - sign * sw), C45 * (sign * cw + sw));
    float2 v6 = cmulf(z6, -sign * sw, sign * cw);
    float2 v7 = cmulf(z7, C45 * (-cw - sign * sw), C45 * (sign * cw - sw));
    x[0] = cadd(z0, v4); x[4] = csub(z0, v4);
    x[1] = cadd(z1, v5); x[5] = csub(z1, v5);
    x[2] = cadd(z2, v6); x[6] = csub(z2, v6);
    x[3] = cadd(z3, v7); x[7] = csub(z3, v7);
}

// ---------------- fused radix-2^3 DIT pass on PHI-padded smem ----------------
__device__ __forceinline__ void r8_pass(float2* s, int N8, int st, float inv4h, float sign) {
    const int h = 1 << (st - 1);
    for (int g = threadIdx.x; g < N8; g += NTHR) {
        const int jj   = g & (h - 1);
        const int base = ((g >> (st - 1)) << (st + 2)) + jj;
        float2 x[8];
#pragma unroll
        for (int m = 0; m < 8; ++m) x[m] = s[PHI(base + m * h)];
        float sw, cw; sincospif((float)jj * inv4h, &sw, &cw);
        sw *= sign;
        r8_core(x, cw, sw, sign);
#pragma unroll
        for (int m = 0; m < 8; ++m) s[PHI(base + m * h)] = x[m];
    }
    __syncthreads();
}

__device__ __forceinline__ float mirror_val(const float* sc, int i) {
    if (i < 4096)  return sc[4095 - i];
    if (i < 12288) return sc[i - 4096];
    return sc[20479 - i];
}

// ---------------- two-hop grid barrier (epoch-monotonic targets) -------------
__device__ __forceinline__ void gsync_plain(unsigned target) {
    __syncthreads();
    if (threadIdx.x == 0) {
        __threadfence();
        asm volatile("st.global.release.gpu.b32 [%0], %1;"
                     :: "l"(&g_flags[blockIdx.x]), "r"(target) : "memory");
    }
    if (blockIdx.x == 0) {
        if (threadIdx.x < NBLK) {
            unsigned w;
            do {
                asm volatile("ld.global.acquire.gpu.b32 %0, [%1];"
                             : "=r"(w) : "l"(&g_flags[threadIdx.x]) : "memory");
            } while (w < target);
        }
        __syncthreads();
        if (threadIdx.x == 0) {
            asm volatile("st.global.release.gpu.b32 [%0], %1;"
                         :: "l"(&g_gen), "r"(target) : "memory");
        }
    } else {
        if (threadIdx.x == 0) {
            unsigned w;
            do {
                asm volatile("ld.global.acquire.gpu.b32 %0, [%1];"
                             : "=r"(w) : "l"(&g_gen) : "memory");
            } while (w < target);
        }
    }
    __syncthreads();
}

// conceptual prep value Zc[q] (q in [0,8192)) for row H (contiguous)
__device__ __forceinline__ float2 prep_val(int q, const float2* __restrict__ H) {
    float2 Hk, HM;
    if (q == 0) {
        Hk = make_float2(H[0].x, 0.f);
        HM = make_float2(H[HF - 1].x, 0.f);
    } else {
        Hk = H[q];
        float2 pm = H[HF - q];
        HM = make_float2(pm.x, -pm.y);
    }
    float px = Hk.x + HM.x, py = Hk.y + HM.y;
    float dx = Hk.x - HM.x, dy = Hk.y - HM.y;
    float sp, cp; sincospif((float)q * (1.0f / (float)HF), &sp, &cp);
    float qx = cp * dx - sp * dy, qy = cp * dy + sp * dx;
    return make_float2(px - qy, py + qx);
}

// =============================================================================
// Single fused kernel: fwd FFT (A/B/C) + scan (atomic single-hop) + recon.
// =============================================================================
__global__ __launch_bounds__(NTHR, 1) void mvmd_kernel(const float* __restrict__ sig,
                                                       float* __restrict__ dout,
                                                       int mode, long long limf) {
    extern __shared__ float2 sh[];               // 13056 float2 (104448 B)
    float2* s_tile = sh;                          // phase A/C tile (<=1088)
    float2* s_trb  = sh + 2048;                   // transpose staging 4*16*65 = 4160
    __shared__ float    s_omega[K_MODES];
    __shared__ float    s_wpart[32][17];
    __shared__ unsigned s_ep;

    const int tid  = threadIdx.x;
    const int lane = tid & 31;
    const int wid  = tid >> 5;
    const long long lim2 = limf >> 1;

    if (tid == 0) s_ep = g_epoch;
    if (tid < K_MODES) s_omega[tid] = 0.0625f * (float)tid;
    __syncthreads();
    const unsigned ep = s_ep;

    // zero per-iteration atomic state (block b<19 owns row b); visible after gsync(ep+1)
    if (blockIdx.x < N_ITERS) {
        if (tid == 16) g_itcnt[blockIdx.x] = 0u;
        if (tid < 16)  g_acc[blockIdx.x][tid] = 0ull;
    }
    if (blockIdx.x == 0 && tid < K_MODES) g_omega[tid] = 0.0625f * (float)tid;

    // ---- Phase A: per-(channel, tile) local FFT (stages 1..9) ----
    {
        const int ch = blockIdx.x >> 3;
        const int t8 = blockIdx.x & 7;
        const float* sc = sig + ch * T_LEN;
        for (int bp = tid; bp < 512; bp += NTHR) {
            const int b  = (t8 << 9) + bp;
            const int q0 = __brev((unsigned)b) >> 20;   // r12(b)
            const int q1 = q0 + 4096;
            float2 A = make_float2(mirror_val(sc, 2 * q0), mirror_val(sc, 2 * q0 + 1));
            float2 B = make_float2(mirror_val(sc, 2 * q1), mirror_val(sc, 2 * q1 + 1));
            s_tile[PHI(2 * bp)]     = cadd(A, B);
            s_tile[PHI(2 * bp + 1)] = csub(A, B);
        }
        __syncthreads();
        r8_pass(s_tile, 128, 2, 1.f / 8.f,   -1.f);
        r8_pass(s_tile, 128, 5, 1.f / 64.f,  -1.f);
        r8_pass(s_tile, 128, 8, 1.f / 512.f, -1.f);
        for (int i = tid; i < 1024; i += NTHR)
            g_work[ch][(t8 << 10) + i] = s_tile[PHI(i)];
    }
    gsync_plain(ep + 1u);

    // ---- Phase B: final pass (st=11, h=1024) in global, in-place ----
    if (tid < 128) {
        const int idx = (blockIdx.x << 7) + tid;
        const int ch2 = idx >> 10, gc = idx & 1023;
        float2 x[8];
#pragma unroll
        for (int m = 0; m < 8; ++m) x[m] = g_work[ch2][gc + (m << 10)];
        float sw, cw; sincospif((float)gc * (1.f / 4096.f), &sw, &cw);
        sw = -sw;
        r8_core(x, cw, sw, -1.f);
#pragma unroll
        for (int m = 0; m < 8; ++m) g_work[ch2][gc + (m << 10)] = x[m];
    }
    gsync_plain(ep + 2u);

    // ---- Phase C: coalesced untangle -> per-thread fp via smem exchange ----
    {
        const int a    = tid >> 6;                 // raw channel
        const int jloc = tid & 63;
        const int jj   = (blockIdx.x << 6) + jloc; // frequency bin
        float2 Zk = g_work[a][jj];
        float2 Zm = g_work[a][(HF - jj) & (HF - 1)];
        float ex = 0.5f * (Zk.x + Zm.x), ey = 0.5f * (Zk.y - Zm.y);
        float bx = 0.5f * (Zk.x - Zm.x), by = 0.5f * (Zk.y + Zm.y);
        float ox = by, oy = -bx;
        float sp, cp; sincospif((float)jj * (1.0f / (float)HF), &sp, &cp);
        float fxv = ex + cp * ox + sp * oy;
        float fyv = ey + cp * oy - sp * ox;
        const int cshift = (a + 8) & 15;
        s_tile[jloc * 16 + cshift] = make_float2(fxv, fyv);
    }
    __syncthreads();
    const float2 fp = s_tile[tid];
    __syncthreads();

    // ---- Persistent scan: single-hop deterministic atomic reduction ----
    const int e    = blockIdx.x * NTHR + tid;   // e = j*16 + c_shifted
    const int j    = e >> 4;
    const float fh = (float)j * (1.0f / (float)F_LEN);

    float2 u[K_MODES];
#pragma unroll
    for (int k = 0; k < K_MODES; ++k) u[k] = make_float2(0.f, 0.f);
    float2 sum = make_float2(0.f, 0.f);

    for (int it = 0; it < N_ITERS; ++it) {
        sum.x += u[K_MODES - 1].x - u[0].x;
        sum.y += u[K_MODES - 1].y - u[0].y;
        float2 prev_new = make_float2(0.f, 0.f);
        float v[16];
#pragma unroll
        for (int k = 0; k < K_MODES; ++k) {
            if (k > 0) {
                sum.x += prev_new.x - u[k].x;
                sum.y += prev_new.y - u[k].y;
            }
            float d      = fh - s_omega[k];
            float den    = 1.0f + ALPHA_F * d * d;
            float invden = __fdividef(1.0f, den);
            float2 un    = make_float2((fp.x - sum.x) * invden, (fp.y - sum.y) * invden);
            u[k] = un;
            prev_new = un;
            float mag = un.x * un.x + un.y * un.y;
            v[2 * k + 0] = fh * mag;   // num
            v[2 * k + 1] = mag;        // den
        }
        // 16-value bundled butterfly (16 shfl, depth 5)
        {
            const unsigned FM = 0xffffffffu;
#pragma unroll
            for (int i = 0; i < 8; ++i) {
                float send = (lane & 16) ? v[i] : v[i + 8];
                float recv = __shfl_xor_sync(FM, send, 16);
                v[i] = ((lane & 16) ? v[i + 8] : v[i]) + recv;
            }
#pragma unroll
            for (int i = 0; i < 4; ++i) {
                float send = (lane & 8) ? v[i] : v[i + 4];
                float recv = __shfl_xor_sync(FM, send, 8);
                v[i] = ((lane & 8) ? v[i + 4] : v[i]) + recv;
            }
#pragma unroll
            for (int i = 0; i < 2; ++i) {
                float send = (lane & 4) ? v[i] : v[i + 2];
                float recv = __shfl_xor_sync(FM, send, 4);
                v[i] = ((lane & 4) ? v[i + 2] : v[i]) + recv;
            }
            {
                float send = (lane & 2) ? v[0] : v[1];
                float recv = __shfl_xor_sync(FM, send, 2);
                v[0] = ((lane & 2) ? v[1] : v[0]) + recv;
            }
            v[0] += __shfl_xor_sync(FM, v[0], 1);
            if ((lane & 1) == 0) s_wpart[wid][lane >> 1] = v[0];
        }
        __syncthreads();
        if (tid < 512) {
            const int vv = tid >> 5;
            float acc = s_wpart[lane][vv];
#pragma unroll
            for (int o = 16; o; o >>= 1) acc += __shfl_down_sync(0xffffffffu, acc, o);
            if (lane == 0) {
                // deterministic: exact integer accumulation, order-independent
                unsigned long long q = (unsigned long long)((double)acc * FIXSCALE);
                atomicAdd(&g_acc[it][vv], q);
                __threadfence();
                atomicAdd(&g_itcnt[it], 1u);
            }
        }
        // every block computes omega itself from the exact global integers
        if (tid < K_MODES) {
            unsigned w;
            do {
                asm volatile("ld.global.acquire.gpu.b32 %0, [%1];"
                             : "=r"(w) : "l"(&g_itcnt[it]) : "memory");
            } while (w < (unsigned)(NBLK * 16));
            unsigned long long qn = __ldcg(&g_acc[it][2 * tid]);
            unsigned long long qd = __ldcg(&g_acc[it][2 * tid + 1]);
            float om = (float)((double)qn / (double)qd);   // scale cancels exactly
            s_omega[tid] = om;
            if (blockIdx.x == 0) g_omega[(it + 1) * K_MODES + tid] = om;
        }
        __syncthreads();
    }

    // ---- transposed, coalesced publish of u: g_u2[(k*16+c)*8192 + j] ----
    {
        const int c    = e & 15;       // c_shifted
        const int jloc = tid >> 4;     // 0..63
        const int jbase = blockIdx.x << 6;
#pragma unroll
        for (int half = 0; half < 2; ++half) {
#pragma unroll
            for (int k = 0; k < 4; ++k) s_trb[(k * 16 + c) * 65 + jloc] = u[half * 4 + k];
            __syncthreads();
#pragma unroll
            for (int p = 0; p < 4; ++p) {
                const int idx = p * NTHR + tid;   // 0..4095
                const int r   = idx >> 6;          // 0..63
                const int jl  = idx & 63;
                g_u2[(size_t)(half * 64 + r) * HF + jbase + jl] = s_trb[r * 65 + jl];
            }
            __syncthreads();
        }
    }
    gsync_plain(ep + 3u);
    if (blockIdx.x == 0 && tid == 0) g_epoch = ep + 3u;   // replay-safe epoch advance

    // =========================== RECON PHASE =================================
    float2* sh1 = sh;             // PHI-padded 8704 float2
    float2* sh2 = sh + 8704;      // PHI-padded 4352 float2
    float*  rey = (float*)sh;     // overlays sh1 (dead by then)
    float*  imy = ((float*)sh) + 4608;
    const int b = blockIdx.x;
    const int k = b >> 4;
    const int c = b & 15;
    const float2* __restrict__ H = g_u2 + (size_t)(k * 16 + c) * HF;

    if (b == 0 && tid < (N_ITERS + 1) * K_MODES) {
        float om = g_omega[tid];
        if (mode == MODE_R) {
            long long idx = 2097152LL + tid;
            if (idx < limf) dout[idx] = om;
        } else {
            long long base2 = (mode == MODE_M) ? 1572864LL : 2097152LL;
            long long idx = base2 + tid;
            if (idx < lim2) ((float2*)dout)[idx] = make_float2(om, 0.f);
        }
    }

    for (int bb = tid; bb < 4096; bb += NTHR) {
        const int q0 = __brev((unsigned)bb) >> 20;
        float2 A = prep_val(q0, H);
        float2 B = prep_val(q0 + 4096, H);
        sh1[PHI(2 * bb)]     = cadd(A, B);
        sh1[PHI(2 * bb + 1)] = csub(A, B);
    }
    __syncthreads();
    r8_pass(sh1, 1024, 2,  1.f / 8.f,    +1.f);
    r8_pass(sh1, 1024, 5,  1.f / 64.f,   +1.f);
    r8_pass(sh1, 1024, 8,  1.f / 512.f,  +1.f);
    r8_pass(sh1, 1024, 11, 1.f / 4096.f, +1.f);

    const float invN = 1.0f / (float)F_LEN;
    const int cs = (c + 8) & 15;
    for (int n = tid; n < 4096; n += NTHR) {
        float2 z = sh1[PHI(2048 + n)];
        float w0 = z.x * invN, w1 = z.y * invN;
        long long i0 = (long long)(k * T_LEN + 2 * n) * C_CH + cs;
        long long i1 = i0 + C_CH;
        if (mode == MODE_C) {
            float2* o = (float2*)dout;
            if (i0 < lim2) o[i0] = make_float2(w0, 0.f);
            if (i1 < lim2) o[i1] = make_float2(w1, 0.f);
        } else {
            if (i0 < limf) dout[i0] = w0;
            if (i1 < limf) dout[i1] = w1;
        }
        sh2[PHI(__brev((unsigned)n) >> 20)] = make_float2(w0, w1);
    }
    __syncthreads();
    r8_pass(sh2, 512, 1,  1.f / 4.f,    -1.f);
    r8_pass(sh2, 512, 4,  1.f / 32.f,   -1.f);
    r8_pass(sh2, 512, 7,  1.f / 256.f,  -1.f);
    r8_pass(sh2, 512, 10, 1.f / 2048.f, -1.f);

    for (int q = tid; q < 4096; q += NTHR) {
        float2 Zk = sh2[PHI(q)];
        float2 Zm = sh2[PHI((4096 - q) & 4095)];
        float ex = 0.5f * (Zk.x + Zm.x), ey = 0.5f * (Zk.y - Zm.y);
        float bx = 0.5f * (Zk.x - Zm.x), by = 0.5f * (Zk.y + Zm.y);
        float ox = by, oy = -bx;
        float sp, cp; sincospif((float)q * (1.0f / 4096.0f), &sp, &cp);
        rey[q] = ex + cp * ox + sp * oy;
        imy[q] = ey + cp * oy - sp * ox;
        if (q == 0) { rey[4096] = Zk.x - Zk.y; imy[4096] = 0.f; }
    }
    __syncthreads();

    if (mode == MODE_R) {
        const long long base = (long long)T_LEN * K_MODES * C_CH;
        for (int t = tid; t < T_LEN; t += NTHR) {
            int bb2 = t ^ 4096;
            int rb = (bb2 <= 4096) ? bb2 : 8192 - bb2;
            long long idx = base + ((long long)t * K_MODES + k) * C_CH + c;
            if (idx < limf) dout[idx] = rey[rb];
        }
    } else {
        const long long base2 = (mode == MODE_M)
            ? (long long)(T_LEN * K_MODES * C_CH / 2)
            : (long long)(T_LEN * K_MODES * C_CH);
        float2* o = (float2*)dout;
        for (int t = tid; t < T_LEN; t += NTHR) {
            int bb2 = t ^ 4096;
            float re, im;
            if (bb2 <= 4096) { re = rey[bb2];        im = -imy[bb2]; }
            else             { re = rey[8192 - bb2]; im =  imy[8192 - bb2]; }
            long long idx = base2 + ((long long)t * K_MODES + k) * C_CH + c;
            if (idx < lim2) o[idx] = make_float2(re, im);
        }
    }
}

// ---------------- launch ----------------
extern "C" void kernel_launch(void* const* d_in, const int* in_sizes, int n_in,
                              void* d_out, int out_size) {
    const float* sig = (const float*)d_in[0];

    int mode;
    if (out_size == 4194624)      mode = MODE_C;
    else if (out_size == 3146048) mode = MODE_M;
    else                          mode = MODE_R;
    const long long limf = (long long)out_size;

    const int SMEM = (8704 + 4352) * 8;   // 104448 B
    cudaFuncSetAttribute(mvmd_kernel, cudaFuncAttributeMaxDynamicSharedMemorySize, SMEM);

    mvmd_kernel<<<NBLK, NTHR, SMEM>>>(sig, (float*)d_out, mode, limf);
}

// round 14
// speedup vs baseline: 1.0132x; 1.0132x over previous
#include <cuda_runtime.h>
#include <math.h>

#define C_CH   16
#define T_LEN  8192
#define F_LEN  16384
#define HF     8192
#define K_MODES 8
#define N_ITERS 19
#define ALPHA_F 2000.0f
#define NBLK   128
#define NTHR   1024
#define NANB   0x7FC00000u

#define MODE_R 0   // all-float32: [u_out | Re(u_hat2) | Re(omega)] (2,097,312 f32) -- confirmed
#define MODE_C 1
#define MODE_M 2

// padded smem index: 1 extra float2 per 16 -> breaks power-of-2 stride conflicts
#define PHI(i) ((i) + ((i) >> 4))

// ---------------- device state ----------------
__device__ float2   g_work[C_CH][HF];          // forward-FFT workspace (raw channel)
__device__ float2   g_u2[128 * HF];            // final u, row r=k*16+c_shifted, contiguous j
__device__ float    g_part[2][NBLK][16];       // double-buffered per-block partials
__device__ float    g_omega[(N_ITERS + 1) * K_MODES];
__device__ unsigned g_flags[NBLK];
__device__ unsigned g_gen;

// ---------------- complex helpers ----------------
__device__ __forceinline__ float2 cmulf(float2 a, float c, float s) {
    return make_float2(a.x * c - a.y * s, a.x * s + a.y * c);
}
__device__ __forceinline__ float2 cadd(float2 a, float2 b) { return make_float2(a.x + b.x, a.y + b.y); }
__device__ __forceinline__ float2 csub(float2 a, float2 b) { return make_float2(a.x - b.x, a.y - b.y); }

// ---------------- radix-8 butterfly core ----------
__device__ __forceinline__ void r8_core(float2* x, float cw, float sw, float sign) {
    const float c2 = cw * cw - sw * sw, s2 = 2.f * cw * sw;   // w^2
    const float c1 = c2 * c2 - s2 * s2, s1 = 2.f * c2 * s2;   // w^4
    float2 t1 = cmulf(x[1], c1, s1);
    float2 y0 = cadd(x[0], t1), y1 = csub(x[0], t1);
    float2 t3 = cmulf(x[3], c1, s1);
    float2 y2 = cadd(x[2], t3), y3 = csub(x[2], t3);
    float2 t5 = cmulf(x[5], c1, s1);
    float2 y4 = cadd(x[4], t5), y5 = csub(x[4], t5);
    float2 t7 = cmulf(x[7], c1, s1);
    float2 y6 = cadd(x[6], t7), y7 = csub(x[6], t7);
    const float fx = -sign * s2, fy = sign * c2;
    float2 u2 = cmulf(y2, c2, s2);
    float2 z0 = cadd(y0, u2), z2 = csub(y0, u2);
    float2 u3 = cmulf(y3, fx, fy);
    float2 z1 = cadd(y1, u3), z3 = csub(y1, u3);
    float2 u6 = cmulf(y6, c2, s2);
    float2 z4 = cadd(y4, u6), z6 = csub(y4, u6);
    float2 u7 = cmulf(y7, fx, fy);
    float2 z5 = cadd(y5, u7), z7 = csub(y5, u7);
    const float C45 = 0.70710678118654752440f;
    float2 v4 = cmulf(z4, cw, sw);
    float2 v5 = cmulf(z5, C45 * (cw - sign * sw), C45 * (sign * cw + sw));
    float2 v6 = cmulf(z6, -sign * sw, sign * cw);
    float2 v7 = cmulf(z7, C45 * (-cw - sign * sw), C45 * (sign * cw - sw));
    x[0] = cadd(z0, v4); x[4] = csub(z0, v4);
    x[1] = cadd(z1, v5); x[5] = csub(z1, v5);
    x[2] = cadd(z2, v6); x[6] = csub(z2, v6);
    x[3] = cadd(z3, v7); x[7] = csub(z3, v7);
}

// ---------------- fused radix-2^3 DIT pass on PHI-padded smem ----------------
__device__ __forceinline__ void r8_pass(float2* s, int N8, int st, float inv4h, float sign) {
    const int h = 1 << (st - 1);
    for (int g = threadIdx.x; g < N8; g += NTHR) {
        const int jj   = g & (h - 1);
        const int base = ((g >> (st - 1)) << (st + 2)) + jj;
        float2 x[8];
#pragma unroll
        for (int m = 0; m < 8; ++m) x[m] = s[PHI(base + m * h)];
        float sw, cw; sincospif((float)jj * inv4h, &sw, &cw);
        sw *= sign;
        r8_core(x, cw, sw, sign);
#pragma unroll
        for (int m = 0; m < 8; ++m) s[PHI(base + m * h)] = x[m];
    }
    __syncthreads();
}

__device__ __forceinline__ float mirror_val(const float* sc, int i) {
    if (i < 4096)  return sc[4095 - i];
    if (i < 12288) return sc[i - 4096];
    return sc[20479 - i];
}

// ---------------- two-hop grid barrier (monotonic targets; phase use) -------
__device__ __forceinline__ void flag_arrive(unsigned target) {
    if (threadIdx.x == 0) {
        __threadfence();
        asm volatile("st.global.release.gpu.b32 [%0], %1;"
                     :: "l"(&g_flags[blockIdx.x]), "r"(target) : "memory");
    }
}
__device__ __forceinline__ void gsync_plain(unsigned target) {
    __syncthreads();
    flag_arrive(target);
    if (blockIdx.x == 0) {
        if (threadIdx.x < NBLK) {
            unsigned w;
            do {
                asm volatile("ld.global.acquire.gpu.b32 %0, [%1];"
                             : "=r"(w) : "l"(&g_flags[threadIdx.x]) : "memory");
            } while (w < target);
        }
        __syncthreads();
        if (threadIdx.x == 0) {
            asm volatile("st.global.release.gpu.b32 [%0], %1;"
                         :: "l"(&g_gen), "r"(target) : "memory");
        }
    } else {
        if (threadIdx.x == 0) {
            unsigned w;
            do {
                asm volatile("ld.global.acquire.gpu.b32 %0, [%1];"
                             : "=r"(w) : "l"(&g_gen) : "memory");
            } while (w < target);
        }
    }
    __syncthreads();
}

// =============================================================================
// Fused kernel: distributed forward FFT (phases A/B/C) + persistent scan.
// =============================================================================
__global__ __launch_bounds__(NTHR, 1) void iterate_kernel(const float* __restrict__ sig) {
    const int tid  = threadIdx.x;
    const int lane = tid & 31;
    const int wid  = tid >> 5;

    __shared__ float2 s_tile[1088];          // PHI-padded 1024-tile; reused as s_fp
    __shared__ float2 s_tr[4][C_CH][65];     // transpose staging (one k-half)
    __shared__ float  s_omega[K_MODES];
    __shared__ float  s_wpart[32][17];
    __shared__ float  s_red[16];

    if (tid < K_MODES) s_omega[tid] = 0.0625f * (float)tid;
    if (blockIdx.x == 0) {
        if (tid < K_MODES) g_omega[tid] = 0.0625f * (float)tid;
        if (tid >= 32 && tid < 32 + N_ITERS * K_MODES)
            g_omega[K_MODES + (tid - 32)] = __uint_as_float(NANB);   // NaN sentinels rows 1..19
    }

    // ---- Phase A: per-(channel, tile) local FFT (stages 1..9) ----
    {
        const int ch = blockIdx.x >> 3;
        const int t8 = blockIdx.x & 7;
        const float* sc = sig + ch * T_LEN;
        for (int bp = tid; bp < 512; bp += NTHR) {
            const int b  = (t8 << 9) + bp;
            const int q0 = __brev((unsigned)b) >> 20;   // r12(b)
            const int q1 = q0 + 4096;
            float2 A = make_float2(mirror_val(sc, 2 * q0), mirror_val(sc, 2 * q0 + 1));
            float2 B = make_float2(mirror_val(sc, 2 * q1), mirror_val(sc, 2 * q1 + 1));
            s_tile[PHI(2 * bp)]     = cadd(A, B);
            s_tile[PHI(2 * bp + 1)] = csub(A, B);
        }
        __syncthreads();
        r8_pass(s_tile, 128, 2, 1.f / 8.f,   -1.f);
        r8_pass(s_tile, 128, 5, 1.f / 64.f,  -1.f);
        r8_pass(s_tile, 128, 8, 1.f / 512.f, -1.f);
        for (int i = tid; i < 1024; i += NTHR)
            g_work[ch][(t8 << 10) + i] = s_tile[PHI(i)];
    }
    gsync_plain(1u);

    // ---- Phase B: final pass (st=11, h=1024) in global, in-place ----
    if (tid < 128) {
        const int idx = (blockIdx.x << 7) + tid;
        const int ch2 = idx >> 10, gc = idx & 1023;
        float2 x[8];
#pragma unroll
        for (int m = 0; m < 8; ++m) x[m] = g_work[ch2][gc + (m << 10)];
        float sw, cw; sincospif((float)gc * (1.f / 4096.f), &sw, &cw);
        sw = -sw;
        r8_core(x, cw, sw, -1.f);
#pragma unroll
        for (int m = 0; m < 8; ++m) g_work[ch2][gc + (m << 10)] = x[m];
    }
    gsync_plain(2u);

    // ---- Phase C: coalesced untangle -> per-thread fp via smem exchange ----
    {
        const int a    = tid >> 6;                 // raw channel
        const int jloc = tid & 63;
        const int jj   = (blockIdx.x << 6) + jloc; // frequency bin
        float2 Zk = g_work[a][jj];
        float2 Zm = g_work[a][(HF - jj) & (HF - 1)];
        float ex = 0.5f * (Zk.x + Zm.x), ey = 0.5f * (Zk.y - Zm.y);
        float bx = 0.5f * (Zk.x - Zm.x), by = 0.5f * (Zk.y + Zm.y);
        float ox = by, oy = -bx;
        float sp, cp; sincospif((float)jj * (1.0f / (float)HF), &sp, &cp);
        float fxv = ex + cp * ox + sp * oy;
        float fyv = ey + cp * oy - sp * ox;
        const int cshift = (a + 8) & 15;
        s_tile[jloc * 16 + cshift] = make_float2(fxv, fyv);
    }
    __syncthreads();
    const float2 fp = s_tile[tid];
    __syncthreads();

    // ---- Persistent scan ----
    const int e    = blockIdx.x * NTHR + tid;   // e = j*16 + c_shifted
    const int j    = e >> 4;
    const float fh = (float)j * (1.0f / (float)F_LEN);

    float2 u[K_MODES];
#pragma unroll
    for (int k = 0; k < K_MODES; ++k) u[k] = make_float2(0.f, 0.f);
    float2 sum = make_float2(0.f, 0.f);

    for (int it = 0; it < N_ITERS; ++it) {
        const unsigned target = (unsigned)(it + 3);
        const int buf = it & 1;
        sum.x += u[K_MODES - 1].x - u[0].x;
        sum.y += u[K_MODES - 1].y - u[0].y;
        float2 prev_new = make_float2(0.f, 0.f);
        float v[16];
#pragma unroll
        for (int k = 0; k < K_MODES; ++k) {
            if (k > 0) {
                sum.x += prev_new.x - u[k].x;
                sum.y += prev_new.y - u[k].y;
            }
            float d      = fh - s_omega[k];
            float den    = 1.0f + ALPHA_F * d * d;
            float invden = __fdividef(1.0f, den);
            float2 un    = make_float2((fp.x - sum.x) * invden, (fp.y - sum.y) * invden);
            u[k] = un;
            prev_new = un;
            float mag = un.x * un.x + un.y * un.y;
            v[2 * k + 0] = fh * mag;   // num
            v[2 * k + 1] = mag;        // den
        }
        // 16-value bundled butterfly (16 shfl, depth 5)
        {
            const unsigned FM = 0xffffffffu;
#pragma unroll
            for (int i = 0; i < 8; ++i) {
                float send = (lane & 16) ? v[i] : v[i + 8];
                float recv = __shfl_xor_sync(FM, send, 16);
                v[i] = ((lane & 16) ? v[i + 8] : v[i]) + recv;
            }
#pragma unroll
            for (int i = 0; i < 4; ++i) {
                float send = (lane & 8) ? v[i] : v[i + 4];
                float recv = __shfl_xor_sync(FM, send, 8);
                v[i] = ((lane & 8) ? v[i + 4] : v[i]) + recv;
            }
#pragma unroll
            for (int i = 0; i < 2; ++i) {
                float send = (lane & 4) ? v[i] : v[i + 2];
                float recv = __shfl_xor_sync(FM, send, 4);
                v[i] = ((lane & 4) ? v[i + 2] : v[i]) + recv;
            }
            {
                float send = (lane & 2) ? v[0] : v[1];
                float recv = __shfl_xor_sync(FM, send, 2);
                v[0] = ((lane & 2) ? v[1] : v[0]) + recv;
            }
            v[0] += __shfl_xor_sync(FM, v[0], 1);
            if ((lane & 1) == 0) s_wpart[wid][lane >> 1] = v[0];
        }
        __syncthreads();
        if (tid < 512) {
            const int vv = tid >> 5;
            float acc = s_wpart[lane][vv];
#pragma unroll
            for (int o = 16; o; o >>= 1) acc += __shfl_down_sync(0xffffffffu, acc, o);
            if (lane == 0) g_part[buf][blockIdx.x][vv] = acc;
        }
        __syncthreads();
        flag_arrive(target);
        if (blockIdx.x == 0) {
            // fused poll+gather: each gather thread batch-polls its 4 row flags
            if (tid < 512) {
                const int vv = tid >> 5;
                unsigned a0, a1, a2, a3;
                do {
                    asm volatile("ld.global.acquire.gpu.b32 %0, [%1];"
                                 : "=r"(a0) : "l"(&g_flags[lane]) : "memory");
                    asm volatile("ld.global.acquire.gpu.b32 %0, [%1];"
                                 : "=r"(a1) : "l"(&g_flags[lane + 32]) : "memory");
                    asm volatile("ld.global.acquire.gpu.b32 %0, [%1];"
                                 : "=r"(a2) : "l"(&g_flags[lane + 64]) : "memory");
                    asm volatile("ld.global.acquire.gpu.b32 %0, [%1];"
                                 : "=r"(a3) : "l"(&g_flags[lane + 96]) : "memory");
                } while (a0 < target || a1 < target || a2 < target || a3 < target);
                const float* gp = &g_part[buf][0][0];
                float acc = __ldcg(gp + (lane      ) * 16 + vv)
                          + __ldcg(gp + (lane +  32) * 16 + vv)
                          + __ldcg(gp + (lane +  64) * 16 + vv)
                          + __ldcg(gp + (lane +  96) * 16 + vv);
#pragma unroll
                for (int o = 16; o; o >>= 1) acc += __shfl_down_sync(0xffffffffu, acc, o);
                if (lane == 0) s_red[vv] = acc;
            }
            __syncthreads();
            if (tid < K_MODES) s_omega[tid] = s_red[2 * tid] / s_red[2 * tid + 1];
            __syncthreads();
            if (tid == 0) {
                // single-writer broadcast: 7 plain .cg stores + release on word 7
                float* row = &g_omega[(it + 1) * K_MODES];
#pragma unroll
                for (int q = 0; q < 7; ++q)
                    asm volatile("st.global.cg.b32 [%0], %1;"
                                 :: "l"(row + q), "r"(__float_as_uint(s_omega[q])) : "memory");
                asm volatile("st.global.release.gpu.b32 [%0], %1;"
                             :: "l"(row + 7), "r"(__float_as_uint(s_omega[7])) : "memory");
            }
        } else {
            if (tid == 0) {
                const float* row = &g_omega[(it + 1) * K_MODES];
                unsigned w7;
                do {
                    asm volatile("ld.global.acquire.gpu.b32 %0, [%1];"
                                 : "=r"(w7) : "l"(row + 7) : "memory");
                } while (w7 == NANB);
#pragma unroll
                for (int q = 0; q < 7; ++q) {
                    unsigned wq;
                    asm volatile("ld.global.cg.b32 %0, [%1];"
                                 : "=r"(wq) : "l"(row + q) : "memory");
                    s_omega[q] = __uint_as_float(wq);
                }
                s_omega[7] = __uint_as_float(w7);
            }
        }
        __syncthreads();
    }

    // ---- transposed, coalesced publish of u: g_u2[(k*16+c)*8192 + j] ----
    const int c    = e & 15;       // c_shifted
    const int jloc = tid >> 4;     // 0..63
    const int jbase = blockIdx.x << 6;
#pragma unroll
    for (int half = 0; half < 2; ++half) {
#pragma unroll
        for (int k = 0; k < 4; ++k) s_tr[k][c][jloc] = u[half * 4 + k];
        __syncthreads();
#pragma unroll
        for (int p = 0; p < 4; ++p) {
            const int idx = p * NTHR + tid;   // 0..4095
            const int r   = idx >> 6;         // 0..63 (k*16 + c within half)
            const int jl  = idx & 63;
            g_u2[(size_t)(half * 64 + r) * HF + jbase + jl] = s_tr[r >> 4][r & 15][jl];
        }
        __syncthreads();
    }
}

// conceptual prep value Zc[q] (q in [0,8192)) for row H (contiguous)
__device__ __forceinline__ float2 prep_val(int q, const float2* __restrict__ H) {
    float2 Hk, HM;
    if (q == 0) {
        Hk = make_float2(H[0].x, 0.f);
        HM = make_float2(H[HF - 1].x, 0.f);
    } else {
        Hk = H[q];
        float2 pm = H[HF - q];
        HM = make_float2(pm.x, -pm.y);
    }
    float px = Hk.x + HM.x, py = Hk.y + HM.y;
    float dx = Hk.x - HM.x, dy = Hk.y - HM.y;
    float sp, cp; sincospif((float)q * (1.0f / (float)HF), &sp, &cp);
    float qx = cp * dx - sp * dy, qy = cp * dy + sp * dx;
    return make_float2(px - qy, py + qx);
}

// Per (k,c_shifted): irfft-16384 via complex ifft-8192, slice -> u_out;
// then rfft-8192 via complex fft-4096 + untangle -> u_hat2.
__global__ __launch_bounds__(NTHR, 1) void recon_kernel(float* __restrict__ dout, int mode,
                                                        long long limf) {
    extern __shared__ float2 sh[];
    float2* sh1 = sh;             // PHI-padded 8704 float2
    float2* sh2 = sh + 8704;      // PHI-padded 4352 float2
    float*  rey = (float*)sh;     // overlays sh1 (dead by then)
    float*  imy = ((float*)sh) + 4608;
    const int b   = blockIdx.x;
    const int k   = b >> 4;
    const int c   = b & 15;
    const int tid = threadIdx.x;
    const long long lim2 = limf >> 1;
    const float2* __restrict__ H = g_u2 + (size_t)(k * 16 + c) * HF;

    // reset barrier state for next graph replay
    if (tid == 0) g_flags[b] = 0u;
    if (b == 0 && tid == 1) g_gen = 0u;

    if (b == 0 && tid < (N_ITERS + 1) * K_MODES) {
        float om = g_omega[tid];
        if (mode == MODE_R) {
            long long idx = 2097152LL + tid;
            if (idx < limf) dout[idx] = om;
        } else {
            long long base2 = (mode == MODE_M) ? 1572864LL : 2097152LL;
            long long idx = base2 + tid;
            if (idx < lim2) ((float2*)dout)[idx] = make_float2(om, 0.f);
        }
    }

    for (int bb = tid; bb < 4096; bb += NTHR) {
        const int q0 = __brev((unsigned)bb) >> 20;
        float2 A = prep_val(q0, H);
        float2 B = prep_val(q0 + 4096, H);
        sh1[PHI(2 * bb)]     = cadd(A, B);
        sh1[PHI(2 * bb + 1)] = csub(A, B);
    }
    __syncthreads();
    r8_pass(sh1, 1024, 2,  1.f / 8.f,    +1.f);
    r8_pass(sh1, 1024, 5,  1.f / 64.f,   +1.f);
    r8_pass(sh1, 1024, 8,  1.f / 512.f,  +1.f);
    r8_pass(sh1, 1024, 11, 1.f / 4096.f, +1.f);

    const float invN = 1.0f / (float)F_LEN;
    const int cs = (c + 8) & 15;
    for (int n = tid; n < 4096; n += NTHR) {
        float2 z = sh1[PHI(2048 + n)];
        float w0 = z.x * invN, w1 = z.y * invN;
        long long i0 = (long long)(k * T_LEN + 2 * n) * C_CH + cs;
        long long i1 = i0 + C_CH;
        if (mode == MODE_C) {
            float2* o = (float2*)dout;
            if (i0 < lim2) o[i0] = make_float2(w0, 0.f);
            if (i1 < lim2) o[i1] = make_float2(w1, 0.f);
        } else {
            if (i0 < limf) dout[i0] = w0;
            if (i1 < limf) dout[i1] = w1;
        }
        sh2[PHI(__brev((unsigned)n) >> 20)] = make_float2(w0, w1);
    }
    __syncthreads();
    r8_pass(sh2, 512, 1,  1.f / 4.f,    -1.f);
    r8_pass(sh2, 512, 4,  1.f / 32.f,   -1.f);
    r8_pass(sh2, 512, 7,  1.f / 256.f,  -1.f);
    r8_pass(sh2, 512, 10, 1.f / 2048.f, -1.f);

    for (int q = tid; q < 4096; q += NTHR) {
        float2 Zk = sh2[PHI(q)];
        float2 Zm = sh2[PHI((4096 - q) & 4095)];
        float ex = 0.5f * (Zk.x + Zm.x), ey = 0.5f * (Zk.y - Zm.y);
        float bx = 0.5f * (Zk.x - Zm.x), by = 0.5f * (Zk.y + Zm.y);
        float ox = by, oy = -bx;
        float sp, cp; sincospif((float)q * (1.0f / 4096.0f), &sp, &cp);
        rey[q] = ex + cp * ox + sp * oy;
        imy[q] = ey + cp * oy - sp * ox;
        if (q == 0) { rey[4096] = Zk.x - Zk.y; imy[4096] = 0.f; }
    }
    __syncthreads();

    if (mode == MODE_R) {
        const long long base = (long long)T_LEN * K_MODES * C_CH;
        for (int t = tid; t < T_LEN; t += NTHR) {
            int bb2 = t ^ 4096;
            int rb = (bb2 <= 4096) ? bb2 : 8192 - bb2;
            long long idx = base + ((long long)t * K_MODES + k) * C_CH + c;
            if (idx < limf) dout[idx] = rey[rb];
        }
    } else {
        const long long base2 = (mode == MODE_M)
            ? (long long)(T_LEN * K_MODES * C_CH / 2)
            : (long long)(T_LEN * K_MODES * C_CH);
        float2* o = (float2*)dout;
        for (int t = tid; t < T_LEN; t += NTHR) {
            int bb2 = t ^ 4096;
            float re, im;
            if (bb2 <= 4096) { re = rey[bb2];        im = -imy[bb2]; }
            else             { re = rey[8192 - bb2]; im =  imy[8192 - bb2]; }
            long long idx = base2 + ((long long)t * K_MODES + k) * C_CH + c;
            if (idx < lim2) o[idx] = make_float2(re, im);
        }
    }
}

// ---------------- launch ----------------
extern "C" void kernel_launch(void* const* d_in, const int* in_sizes, int n_in,
                              void* d_out, int out_size) {
    const float* sig = (const float*)d_in[0];

    int mode;
    if (out_size == 4194624)      mode = MODE_C;
    else if (out_size == 3146048) mode = MODE_M;
    else                          mode = MODE_R;
    const long long limf = (long long)out_size;

    const int REC_SMEM = (8704 + 4352) * 8;   // 104448 B
    cudaFuncSetAttribute(recon_kernel, cudaFuncAttributeMaxDynamicSharedMemorySize, REC_SMEM);

    iterate_kernel<<<NBLK, NTHR>>>(sig);
    recon_kernel<<<NBLK, NTHR, REC_SMEM>>>((float*)d_out, mode, limf);
}

// round 15
// speedup vs baseline: 1.2396x; 1.2235x over previous
#include <cuda_runtime.h>
#include <math.h>

#define C_CH   16
#define T_LEN  8192
#define F_LEN  16384
#define HF     8192
#define K_MODES 8
#define N_ITERS 19
#define ALPHA_F 2000.0f
#define NBLK   128
#define NTHR   1024
#define NANB   0x7FC00000u

#define MODE_R 0   // all-float32: [u_out | Re(u_hat2) | Re(omega)] (2,097,312 f32) -- confirmed
#define MODE_C 1
#define MODE_M 2

// padded smem index: 1 extra float2 per 16 -> breaks power-of-2 stride conflicts
#define PHI(i) ((i) + ((i) >> 4))

// ---------------- device state ----------------
__device__ float2   g_work[C_CH][HF];          // forward-FFT workspace (raw channel)
__device__ float2   g_u2[128 * HF];            // final u, row r=k*16+c_shifted, contiguous j
__device__ float    g_part[2][NBLK][16];       // double-buffered per-block partials
__device__ float    g_omega[(N_ITERS + 1) * K_MODES];
__device__ unsigned g_flags[NBLK];
__device__ unsigned g_gen;

// ---------------- complex helpers ----------------
__device__ __forceinline__ float2 cmulf(float2 a, float c, float s) {
    return make_float2(a.x * c - a.y * s, a.x * s + a.y * c);
}
__device__ __forceinline__ float2 cadd(float2 a, float2 b) { return make_float2(a.x + b.x, a.y + b.y); }
__device__ __forceinline__ float2 csub(float2 a, float2 b) { return make_float2(a.x - b.x, a.y - b.y); }

// ---------------- radix-8 butterfly core ----------
__device__ __forceinline__ void r8_core(float2* x, float cw, float sw, float sign) {
    const float c2 = cw * cw - sw * sw, s2 = 2.f * cw * sw;   // w^2
    const float c1 = c2 * c2 - s2 * s2, s1 = 2.f * c2 * s2;   // w^4
    float2 t1 = cmulf(x[1], c1, s1);
    float2 y0 = cadd(x[0], t1), y1 = csub(x[0], t1);
    float2 t3 = cmulf(x[3], c1, s1);
    float2 y2 = cadd(x[2], t3), y3 = csub(x[2], t3);
    float2 t5 = cmulf(x[5], c1, s1);
    float2 y4 = cadd(x[4], t5), y5 = csub(x[4], t5);
    float2 t7 = cmulf(x[7], c1, s1);
    float2 y6 = cadd(x[6], t7), y7 = csub(x[6], t7);
    const float fx = -sign * s2, fy = sign * c2;
    float2 u2 = cmulf(y2, c2, s2);
    float2 z0 = cadd(y0, u2), z2 = csub(y0, u2);
    float2 u3 = cmulf(y3, fx, fy);
    float2 z1 = cadd(y1, u3), z3 = csub(y1, u3);
    float2 u6 = cmulf(y6, c2, s2);
    float2 z4 = cadd(y4, u6), z6 = csub(y4, u6);
    float2 u7 = cmulf(y7, fx, fy);
    float2 z5 = cadd(y5, u7), z7 = csub(y5, u7);
    const float C45 = 0.70710678118654752440f;
    float2 v4 = cmulf(z4, cw, sw);
    float2 v5 = cmulf(z5, C45 * (cw - sign * sw), C45 * (sign * cw + sw));
    float2 v6 = cmulf(z6, -sign * sw, sign * cw);
    float2 v7 = cmulf(z7, C45 * (-cw - sign * sw), C45 * (sign * cw - sw));
    x[0] = cadd(z0, v4); x[4] = csub(z0, v4);
    x[1] = cadd(z1, v5); x[5] = csub(z1, v5);
    x[2] = cadd(z2, v6); x[6] = csub(z2, v6);
    x[3] = cadd(z3, v7); x[7] = csub(z3, v7);
}

// ---------------- fused radix-2^3 DIT pass on PHI-padded smem ----------------
__device__ __forceinline__ void r8_pass(float2* s, int N8, int st, float inv4h, float sign) {
    const int h = 1 << (st - 1);
    for (int g = threadIdx.x; g < N8; g += NTHR) {
        const int jj   = g & (h - 1);
        const int base = ((g >> (st - 1)) << (st + 2)) + jj;
        float2 x[8];
#pragma unroll
        for (int m = 0; m < 8; ++m) x[m] = s[PHI(base + m * h)];
        float sw, cw; sincospif((float)jj * inv4h, &sw, &cw);
        sw *= sign;
        r8_core(x, cw, sw, sign);
#pragma unroll
        for (int m = 0; m < 8; ++m) s[PHI(base + m * h)] = x[m];
    }
    __syncthreads();
}

__device__ __forceinline__ float mirror_val(const float* sc, int i) {
    if (i < 4096)  return sc[4095 - i];
    if (i < 12288) return sc[i - 4096];
    return sc[20479 - i];
}

// ---------------- two-hop grid barrier (monotonic targets; phase use) -------
// NOTE: no __threadfence needed: prior weak writes are ordered into the
// release store via the preceding __syncthreads (PTX causality transitivity).
__device__ __forceinline__ void flag_arrive(unsigned target) {
    if (threadIdx.x == 0) {
        asm volatile("st.global.release.gpu.b32 [%0], %1;"
                     :: "l"(&g_flags[blockIdx.x]), "r"(target) : "memory");
    }
}
__device__ __forceinline__ void gsync_plain(unsigned target) {
    __syncthreads();
    flag_arrive(target);
    if (blockIdx.x == 0) {
        if (threadIdx.x < NBLK) {
            unsigned w;
            do {
                asm volatile("ld.global.acquire.gpu.b32 %0, [%1];"
                             : "=r"(w) : "l"(&g_flags[threadIdx.x]) : "memory");
            } while (w < target);
        }
        __syncthreads();
        if (threadIdx.x == 0) {
            asm volatile("st.global.release.gpu.b32 [%0], %1;"
                         :: "l"(&g_gen), "r"(target) : "memory");
        }
    } else {
        if (threadIdx.x == 0) {
            unsigned w;
            do {
                asm volatile("ld.global.acquire.gpu.b32 %0, [%1];"
                             : "=r"(w) : "l"(&g_gen) : "memory");
            } while (w < target);
        }
    }
    __syncthreads();
}

// =============================================================================
// Fused kernel: distributed forward FFT (phases A/B/C) + persistent scan.
// =============================================================================
__global__ __launch_bounds__(NTHR, 1) void iterate_kernel(const float* __restrict__ sig) {
    const int tid  = threadIdx.x;
    const int lane = tid & 31;
    const int wid  = tid >> 5;

    __shared__ float2 s_tile[1088];          // PHI-padded 1024-tile; reused as s_fp
    __shared__ float2 s_tr[4][C_CH][65];     // transpose staging (one k-half)
    __shared__ float  s_omega[K_MODES];
    __shared__ float  s_wpart[32][17];
    __shared__ float  s_red[16];

    if (tid < K_MODES) s_omega[tid] = 0.0625f * (float)tid;
    if (blockIdx.x == 0) {
        if (tid < K_MODES) g_omega[tid] = 0.0625f * (float)tid;
        if (tid >= 32 && tid < 32 + N_ITERS * K_MODES)
            g_omega[K_MODES + (tid - 32)] = __uint_as_float(NANB);   // NaN sentinels rows 1..19
    }

    // ---- Phase A: per-(channel, tile) local FFT (stages 1..9) ----
    {
        const int ch = blockIdx.x >> 3;
        const int t8 = blockIdx.x & 7;
        const float* sc = sig + ch * T_LEN;
        for (int bp = tid; bp < 512; bp += NTHR) {
            const int b  = (t8 << 9) + bp;
            const int q0 = __brev((unsigned)b) >> 20;   // r12(b)
            const int q1 = q0 + 4096;
            float2 A = make_float2(mirror_val(sc, 2 * q0), mirror_val(sc, 2 * q0 + 1));
            float2 B = make_float2(mirror_val(sc, 2 * q1), mirror_val(sc, 2 * q1 + 1));
            s_tile[PHI(2 * bp)]     = cadd(A, B);
            s_tile[PHI(2 * bp + 1)] = csub(A, B);
        }
        __syncthreads();
        r8_pass(s_tile, 128, 2, 1.f / 8.f,   -1.f);
        r8_pass(s_tile, 128, 5, 1.f / 64.f,  -1.f);
        r8_pass(s_tile, 128, 8, 1.f / 512.f, -1.f);
        for (int i = tid; i < 1024; i += NTHR)
            g_work[ch][(t8 << 10) + i] = s_tile[PHI(i)];
    }
    gsync_plain(1u);

    // ---- Phase B: final pass (st=11, h=1024) in global, in-place ----
    if (tid < 128) {
        const int idx = (blockIdx.x << 7) + tid;
        const int ch2 = idx >> 10, gc = idx & 1023;
        float2 x[8];
#pragma unroll
        for (int m = 0; m < 8; ++m) x[m] = g_work[ch2][gc + (m << 10)];
        float sw, cw; sincospif((float)gc * (1.f / 4096.f), &sw, &cw);
        sw = -sw;
        r8_core(x, cw, sw, -1.f);
#pragma unroll
        for (int m = 0; m < 8; ++m) g_work[ch2][gc + (m << 10)] = x[m];
    }
    gsync_plain(2u);

    // ---- Phase C: coalesced untangle -> per-thread fp via smem exchange ----
    {
        const int a    = tid >> 6;                 // raw channel
        const int jloc = tid & 63;
        const int jj   = (blockIdx.x << 6) + jloc; // frequency bin
        float2 Zk = g_work[a][jj];
        float2 Zm = g_work[a][(HF - jj) & (HF - 1)];
        float ex = 0.5f * (Zk.x + Zm.x), ey = 0.5f * (Zk.y - Zm.y);
        float bx = 0.5f * (Zk.x - Zm.x), by = 0.5f * (Zk.y + Zm.y);
        float ox = by, oy = -bx;
        float sp, cp; sincospif((float)jj * (1.0f / (float)HF), &sp, &cp);
        float fxv = ex + cp * ox + sp * oy;
        float fyv = ey + cp * oy - sp * ox;
        const int cshift = (a + 8) & 15;
        s_tile[jloc * 16 + cshift] = make_float2(fxv, fyv);
    }
    __syncthreads();
    const float2 fp = s_tile[tid];
    __syncthreads();

    // ---- Persistent scan ----
    const int e    = blockIdx.x * NTHR + tid;   // e = j*16 + c_shifted
    const int j    = e >> 4;
    const float fh = (float)j * (1.0f / (float)F_LEN);

    float2 u[K_MODES];
#pragma unroll
    for (int k = 0; k < K_MODES; ++k) u[k] = make_float2(0.f, 0.f);
    float2 sum = make_float2(0.f, 0.f);

    for (int it = 0; it < N_ITERS; ++it) {
        const unsigned target = (unsigned)(it + 3);
        const int buf = it & 1;
        sum.x += u[K_MODES - 1].x - u[0].x;
        sum.y += u[K_MODES - 1].y - u[0].y;
        float2 prev_new = make_float2(0.f, 0.f);
        float v[16];
#pragma unroll
        for (int k = 0; k < K_MODES; ++k) {
            if (k > 0) {
                sum.x += prev_new.x - u[k].x;
                sum.y += prev_new.y - u[k].y;
            }
            float d      = fh - s_omega[k];
            float den    = 1.0f + ALPHA_F * d * d;
            float invden = __fdividef(1.0f, den);
            float2 un    = make_float2((fp.x - sum.x) * invden, (fp.y - sum.y) * invden);
            u[k] = un;
            prev_new = un;
            float mag = un.x * un.x + un.y * un.y;
            v[2 * k + 0] = fh * mag;   // num
            v[2 * k + 1] = mag;        // den
        }
        // 16-value bundled butterfly (16 shfl, depth 5)
        {
            const unsigned FM = 0xffffffffu;
#pragma unroll
            for (int i = 0; i < 8; ++i) {
                float send = (lane & 16) ? v[i] : v[i + 8];
                float recv = __shfl_xor_sync(FM, send, 16);
                v[i] = ((lane & 16) ? v[i + 8] : v[i]) + recv;
            }
#pragma unroll
            for (int i = 0; i < 4; ++i) {
                float send = (lane & 8) ? v[i] : v[i + 4];
                float recv = __shfl_xor_sync(FM, send, 8);
                v[i] = ((lane & 8) ? v[i + 4] : v[i]) + recv;
            }
#pragma unroll
            for (int i = 0; i < 2; ++i) {
                float send = (lane & 4) ? v[i] : v[i + 2];
                float recv = __shfl_xor_sync(FM, send, 4);
                v[i] = ((lane & 4) ? v[i + 2] : v[i]) + recv;
            }
            {
                float send = (lane & 2) ? v[0] : v[1];
                float recv = __shfl_xor_sync(FM, send, 2);
                v[0] = ((lane & 2) ? v[1] : v[0]) + recv;
            }
            v[0] += __shfl_xor_sync(FM, v[0], 1);
            if ((lane & 1) == 0) s_wpart[wid][lane >> 1] = v[0];
        }
        __syncthreads();
        if (tid < 512) {
            const int vv = tid >> 5;
            float acc = s_wpart[lane][vv];
#pragma unroll
            for (int o = 16; o; o >>= 1) acc += __shfl_down_sync(0xffffffffu, acc, o);
            if (lane == 0) g_part[buf][blockIdx.x][vv] = acc;
        }
        __syncthreads();
        flag_arrive(target);
        if (blockIdx.x == 0) {
            if (tid < NBLK) {
                unsigned w;
                do {
                    asm volatile("ld.global.acquire.gpu.b32 %0, [%1];"
                                 : "=r"(w) : "l"(&g_flags[tid]) : "memory");
                } while (w < target);
            }
            __syncthreads();
            if (tid < 512) {
                const int vv = tid >> 5;
                const float* gp = &g_part[buf][0][0];
                float acc = __ldcg(gp + (lane      ) * 16 + vv)
                          + __ldcg(gp + (lane +  32) * 16 + vv)
                          + __ldcg(gp + (lane +  64) * 16 + vv)
                          + __ldcg(gp + (lane +  96) * 16 + vv);
#pragma unroll
                for (int o = 16; o; o >>= 1) acc += __shfl_down_sync(0xffffffffu, acc, o);
                if (lane == 0) s_red[vv] = acc;
            }
            __syncthreads();
            if (tid < K_MODES) {
                float om = s_red[2 * tid] / s_red[2 * tid + 1];
                s_omega[tid] = om;
                // the omega row IS the broadcast flag (NaN sentinel scheme)
                asm volatile("st.global.release.gpu.b32 [%0], %1;"
                             :: "l"(&g_omega[(it + 1) * K_MODES + tid]),
                                "r"(__float_as_uint(om)) : "memory");
            }
            __syncthreads();
        } else {
            if (tid < K_MODES) {
                unsigned w;
                do {
                    asm volatile("ld.global.acquire.gpu.b32 %0, [%1];"
                                 : "=r"(w)
                                 : "l"(&g_omega[(it + 1) * K_MODES + tid]) : "memory");
                } while (w == NANB);
                s_omega[tid] = __uint_as_float(w);
            }
            __syncthreads();
        }
    }

    // ---- transposed, coalesced publish of u: g_u2[(k*16+c)*8192 + j] ----
    const int c    = e & 15;       // c_shifted
    const int jloc = tid >> 4;     // 0..63
    const int jbase = blockIdx.x << 6;
#pragma unroll
    for (int half = 0; half < 2; ++half) {
#pragma unroll
        for (int k = 0; k < 4; ++k) s_tr[k][c][jloc] = u[half * 4 + k];
        __syncthreads();
#pragma unroll
        for (int p = 0; p < 4; ++p) {
            const int idx = p * NTHR + tid;   // 0..4095
            const int r   = idx >> 6;         // 0..63 (k*16 + c within half)
            const int jl  = idx & 63;
            g_u2[(size_t)(half * 64 + r) * HF + jbase + jl] = s_tr[r >> 4][r & 15][jl];
        }
        __syncthreads();
    }
}

// prep pair: A = Zc[q], B = Zc[q+4096] sharing ONE sincospif.
// tw((q+4096)/8192*pi) = i * tw(q/8192*pi)  =>  (cpB, spB) = (-sp, cp). Exact.
__device__ __forceinline__ void prep_pair(int q, const float2* __restrict__ H,
                                          float2* A, float2* B) {
    float sp, cp; sincospif((float)q * (1.0f / (float)HF), &sp, &cp);
    // ---- A side (handles q == 0 special) ----
    {
        float2 Hk, HM;
        if (q == 0) {
            Hk = make_float2(H[0].x, 0.f);
            HM = make_float2(H[HF - 1].x, 0.f);
        } else {
            Hk = H[q];
            float2 pm = H[HF - q];
            HM = make_float2(pm.x, -pm.y);
        }
        float px = Hk.x + HM.x, py = Hk.y + HM.y;
        float dx = Hk.x - HM.x, dy = Hk.y - HM.y;
        float qx = cp * dx - sp * dy, qy = cp * dy + sp * dx;
        *A = make_float2(px - qy, py + qx);
    }
    // ---- B side: q' = q + 4096 (never 0); H[HF - q'] = H[4096 - q] ----
    {
        float2 Hk = H[q + 4096];
        float2 pm = H[4096 - q];
        float2 HM = make_float2(pm.x, -pm.y);
        float px = Hk.x + HM.x, py = Hk.y + HM.y;
        float dx = Hk.x - HM.x, dy = Hk.y - HM.y;
        const float cb = -sp, sb = cp;
        float qx = cb * dx - sb * dy, qy = cb * dy + sb * dx;
        *B = make_float2(px - qy, py + qx);
    }
}

// Per (k,c_shifted): irfft-16384 via complex ifft-8192, slice -> u_out;
// then rfft-8192 via complex fft-4096 + untangle -> u_hat2.
__global__ __launch_bounds__(NTHR, 1) void recon_kernel(float* __restrict__ dout, int mode,
                                                        long long limf) {
    extern __shared__ float2 sh[];
    float2* sh1 = sh;             // PHI-padded 8704 float2
    float2* sh2 = sh + 8704;      // PHI-padded 4352 float2
    float*  rey = (float*)sh;     // overlays sh1 (dead by then)
    float*  imy = ((float*)sh) + 4608;
    const int b   = blockIdx.x;
    const int k   = b >> 4;
    const int c   = b & 15;
    const int tid = threadIdx.x;
    const long long lim2 = limf >> 1;
    const float2* __restrict__ H = g_u2 + (size_t)(k * 16 + c) * HF;

    // reset barrier state for next graph replay
    if (tid == 0) g_flags[b] = 0u;
    if (b == 0 && tid == 1) g_gen = 0u;

    if (b == 0 && tid < (N_ITERS + 1) * K_MODES) {
        float om = g_omega[tid];
        if (mode == MODE_R) {
            long long idx = 2097152LL + tid;
            if (idx < limf) dout[idx] = om;
        } else {
            long long base2 = (mode == MODE_M) ? 1572864LL : 2097152LL;
            long long idx = base2 + tid;
            if (idx < lim2) ((float2*)dout)[idx] = make_float2(om, 0.f);
        }
    }

    for (int bb = tid; bb < 4096; bb += NTHR) {
        const int q0 = __brev((unsigned)bb) >> 20;
        float2 A, B;
        prep_pair(q0, H, &A, &B);
        sh1[PHI(2 * bb)]     = cadd(A, B);
        sh1[PHI(2 * bb + 1)] = csub(A, B);
    }
    __syncthreads();
    r8_pass(sh1, 1024, 2,  1.f / 8.f,    +1.f);
    r8_pass(sh1, 1024, 5,  1.f / 64.f,   +1.f);
    r8_pass(sh1, 1024, 8,  1.f / 512.f,  +1.f);
    r8_pass(sh1, 1024, 11, 1.f / 4096.f, +1.f);

    const float invN = 1.0f / (float)F_LEN;
    const int cs = (c + 8) & 15;
    for (int n = tid; n < 4096; n += NTHR) {
        float2 z = sh1[PHI(2048 + n)];
        float w0 = z.x * invN, w1 = z.y * invN;
        long long i0 = (long long)(k * T_LEN + 2 * n) * C_CH + cs;
        long long i1 = i0 + C_CH;
        if (mode == MODE_C) {
            float2* o = (float2*)dout;
            if (i0 < lim2) o[i0] = make_float2(w0, 0.f);
            if (i1 < lim2) o[i1] = make_float2(w1, 0.f);
        } else {
            if (i0 < limf) dout[i0] = w0;
            if (i1 < limf) dout[i1] = w1;
        }
        sh2[PHI(__brev((unsigned)n) >> 20)] = make_float2(w0, w1);
    }
    __syncthreads();
    r8_pass(sh2, 512, 1,  1.f / 4.f,    -1.f);
    r8_pass(sh2, 512, 4,  1.f / 32.f,   -1.f);
    r8_pass(sh2, 512, 7,  1.f / 256.f,  -1.f);
    r8_pass(sh2, 512, 10, 1.f / 2048.f, -1.f);

    // untangle: q = tid + p*1024; angle step pi/4 -> rotate twiddle exactly
    {
        const float C45 = 0.70710678118654752440f;
        float sp, cp; sincospif((float)tid * (1.0f / 4096.0f), &sp, &cp);
#pragma unroll
        for (int p = 0; p < 4; ++p) {
            const int q = tid + p * 1024;
            float2 Zk = sh2[PHI(q)];
            float2 Zm = sh2[PHI((4096 - q) & 4095)];
            float ex = 0.5f * (Zk.x + Zm.x), ey = 0.5f * (Zk.y - Zm.y);
            float bx = 0.5f * (Zk.x - Zm.x), by = 0.5f * (Zk.y + Zm.y);
            float ox = by, oy = -bx;
            rey[q] = ex + cp * ox + sp * oy;
            imy[q] = ey + cp * oy - sp * ox;
            if (q == 0) { rey[4096] = Zk.x - Zk.y; imy[4096] = 0.f; }
            // rotate (cp,sp) by +pi/4 for next p
            float cn = (cp - sp) * C45;
            float sn = (sp + cp) * C45;
            cp = cn; sp = sn;
        }
    }
    __syncthreads();

    if (mode == MODE_R) {
        const long long base = (long long)T_LEN * K_MODES * C_CH;
        for (int t = tid; t < T_LEN; t += NTHR) {
            int bb2 = t ^ 4096;
            int rb = (bb2 <= 4096) ? bb2 : 8192 - bb2;
            long long idx = base + ((long long)t * K_MODES + k) * C_CH + c;
            if (idx < limf) dout[idx] = rey[rb];
        }
    } else {
        const long long base2 = (mode == MODE_M)
            ? (long long)(T_LEN * K_MODES * C_CH / 2)
            : (long long)(T_LEN * K_MODES * C_CH);
        float2* o = (float2*)dout;
        for (int t = tid; t < T_LEN; t += NTHR) {
            int bb2 = t ^ 4096;
            float re, im;
            if (bb2 <= 4096) { re = rey[bb2];        im = -imy[bb2]; }
            else             { re = rey[8192 - bb2]; im =  imy[8192 - bb2]; }
            long long idx = base2 + ((long long)t * K_MODES + k) * C_CH + c;
            if (idx < lim2) o[idx] = make_float2(re, im);
        }
    }
}

// ---------------- launch ----------------
extern "C" void kernel_launch(void* const* d_in, const int* in_sizes, int n_in,
                              void* d_out, int out_size) {
    const float* sig = (const float*)d_in[0];

    int mode;
    if (out_size == 4194624)      mode = MODE_C;
    else if (out_size == 3146048) mode = MODE_M;
    else                          mode = MODE_R;
    const long long limf = (long long)out_size;

    const int REC_SMEM = (8704 + 4352) * 8;   // 104448 B
    cudaFuncSetAttribute(recon_kernel, cudaFuncAttributeMaxDynamicSharedMemorySize, REC_SMEM);

    iterate_kernel<<<NBLK, NTHR>>>(sig);
    recon_kernel<<<NBLK, NTHR, REC_SMEM>>>((float*)d_out, mode, limf);
}